// round 2
// baseline (speedup 1.0000x reference)
#include <cuda_runtime.h>
#include <math.h>

// Problem constants
#define B_   16
#define CIN  32
#define COUT 64
#define H_   64
#define W_   64
#define HO   62
#define WO   62
#define P_   9      // 3x3 kernel positions
#define NG   9      // features per element: silu + 8 spline bases
#define GK   8      // spline basis count
#define HW   (H_*W_)

// Scratch (device globals per harness allocation rules)
__device__ float g_F[B_*CIN*NG*HW];          // [b][c][g][h][w]  ~75.5 MB
__device__ float g_Wf[CIN*NG*P_*COUT];       // [c][g][p][o]     ~663 KB

// ---------------------------------------------------------------------------
// Cubic B-spline bases, Cox-de Boor, matching the reference exactly in fp32.
// knots t[j] = (j-3)*0.4 - 1, j=0..11;  output 8 bases.
// ---------------------------------------------------------------------------
__device__ __forceinline__ void bspline8(float x, float bs[8]) {
    float t[12];
#pragma unroll
    for (int j = 0; j < 12; ++j) t[j] = (float)(j - 3) * 0.4f + (-1.0f);
    float b0[11];
#pragma unroll
    for (int i = 0; i < 11; ++i) b0[i] = (x >= t[i] && x < t[i + 1]) ? 1.0f : 0.0f;
    float b1[10];
#pragma unroll
    for (int i = 0; i < 10; ++i)
        b1[i] = (x - t[i]) / (t[i + 1] - t[i]) * b0[i]
              + (t[i + 2] - x) / (t[i + 2] - t[i + 1]) * b0[i + 1];
    float b2[9];
#pragma unroll
    for (int i = 0; i < 9; ++i)
        b2[i] = (x - t[i]) / (t[i + 2] - t[i]) * b1[i]
              + (t[i + 3] - x) / (t[i + 3] - t[i + 1]) * b1[i + 1];
#pragma unroll
    for (int i = 0; i < 8; ++i)
        bs[i] = (x - t[i]) / (t[i + 3] - t[i]) * b2[i]
              + (t[i + 4] - x) / (t[i + 4] - t[i + 1]) * b2[i + 1];
}

// ---------------------------------------------------------------------------
// Kernel 1: per-pixel feature map  (silu + 8 bases) -> g_F
// ---------------------------------------------------------------------------
__global__ void feat_kernel(const float* __restrict__ x) {
    int idx = blockIdx.x * blockDim.x + threadIdx.x;
    if (idx >= B_ * CIN * HW) return;
    float v = x[idx];
    int hw = idx & (HW - 1);
    int bc = idx >> 12;                       // HW == 4096
    float* dst = g_F + (size_t)bc * NG * HW + hw;
    dst[0] = v / (1.0f + expf(-v));           // SiLU
    float bs[8];
    bspline8(v, bs);
#pragma unroll
    for (int g = 0; g < 8; ++g) dst[(size_t)(g + 1) * HW] = bs[g];
}

// ---------------------------------------------------------------------------
// Kernel 2: fold weights  Wf[c][g][p][o]
//   g==0 : base_weight[o][c][p]
//   g>=1 : spline_weight[o][c][p][g-1] * spline_scaler[o][c][p]
// ---------------------------------------------------------------------------
__global__ void fold_kernel(const float* __restrict__ bw,
                            const float* __restrict__ sw,
                            const float* __restrict__ ss) {
    int i = blockIdx.x * blockDim.x + threadIdx.x;
    if (i >= CIN * NG * P_ * COUT) return;
    int o = i & 63;
    int r = i >> 6;
    int p = r % P_; r /= P_;
    int g = r % NG;
    int c = r / NG;
    int ocp = (o * CIN + c) * P_ + p;
    float val = (g == 0) ? bw[ocp] : sw[ocp * GK + (g - 1)] * ss[ocp];
    g_Wf[i] = val;
}

// ---------------------------------------------------------------------------
// Kernel 3: implicit-GEMM conv.
// Block = (one output row ho, one batch b), 256 threads.
// Thread: 4 spatial x 4 channels, held as 8 packed f32x2 accumulators.
// smem: feature slab [9g][3rows][66w] + weight slab [9g][9p][64o] per c-iter.
// Inner math uses fma.rn.f32x2 (packed dual FMA -> 2x fp32 rate on sm_103a).
// ---------------------------------------------------------------------------
#define FW 66
#define FS_PAD 2   // pad Fs to 1784 floats (7136 B, multiple of 16)

__global__ void __launch_bounds__(256) conv_kernel(float* __restrict__ out) {
    __shared__ __align__(16) float Fs[NG * 3 * FW + FS_PAD]; // 7136 B
    __shared__ __align__(16) float Ws[NG * P_ * COUT];       // 20736 B, 16B-aligned

    const int ho = blockIdx.x;
    const int b  = blockIdx.y;
    const int t  = threadIdx.x;
    const int o0  = (t & 15) << 2;         // 0..60, step 4
    const int sp0 = (t >> 4) << 2;         // 0..60, step 4

    unsigned long long acc[4][2];
#pragma unroll
    for (int i = 0; i < 4; ++i) { acc[i][0] = 0ull; acc[i][1] = 0ull; }

    for (int c = 0; c < CIN; ++c) {
        const float* Fb = g_F + ((size_t)(b * CIN + c) * NG) * HW;
        for (int i = t; i < NG * 3 * FW; i += 256) {
            int w  = i % FW;
            int gr = i / FW;
            int g  = gr / 3;
            int r  = gr - 3 * g;
            Fs[i] = (w < W_) ? Fb[(size_t)g * HW + (ho + r) * W_ + w] : 0.0f;
        }
        const float* Wc = g_Wf + (size_t)c * (NG * P_ * COUT);
        for (int i = t; i < NG * P_ * COUT; i += 256) Ws[i] = Wc[i];
        __syncthreads();

#pragma unroll
        for (int g = 0; g < NG; ++g) {
            // pack feature window (3 rows x 6 cols) into (v,v) f32x2 pairs
            unsigned long long fp[3][6];
#pragma unroll
            for (int r = 0; r < 3; ++r)
#pragma unroll
                for (int j = 0; j < 6; ++j) {
                    unsigned int vb = __float_as_uint(Fs[(g * 3 + r) * FW + sp0 + j]);
                    asm("mov.b64 %0, {%1, %1};" : "=l"(fp[r][j]) : "r"(vb));
                }
#pragma unroll
            for (int p = 0; p < P_; ++p) {
                const int kh = p / 3, kw = p % 3;
                ulonglong2 wv = *reinterpret_cast<const ulonglong2*>(
                    &Ws[(g * P_ + p) * COUT + o0]);   // 16B aligned now
#pragma unroll
                for (int i = 0; i < 4; ++i) {
                    asm("fma.rn.f32x2 %0, %1, %2, %0;"
                        : "+l"(acc[i][0]) : "l"(fp[kh][i + kw]), "l"(wv.x));
                    asm("fma.rn.f32x2 %0, %1, %2, %0;"
                        : "+l"(acc[i][1]) : "l"(fp[kh][i + kw]), "l"(wv.y));
                }
            }
        }
        __syncthreads();
    }

    // write back: out[b][o][ho][wo], fp32
#pragma unroll
    for (int i = 0; i < 4; ++i) {
        int wo = sp0 + i;
        if (wo < WO) {
#pragma unroll
            for (int j = 0; j < 2; ++j) {
                unsigned int lo, hi;
                asm("mov.b64 {%0, %1}, %2;" : "=r"(lo), "=r"(hi) : "l"(acc[i][j]));
                int o = o0 + 2 * j;
                out[(((size_t)b * COUT + o)     * HO + ho) * WO + wo] = __uint_as_float(lo);
                out[(((size_t)b * COUT + o + 1) * HO + ho) * WO + wo] = __uint_as_float(hi);
            }
        }
    }
}

// ---------------------------------------------------------------------------
// Launch: features + weight-fold (independent), then conv.
// Inputs (metadata order): x, base_weight, spline_weight, spline_scaler.
// ---------------------------------------------------------------------------
extern "C" void kernel_launch(void* const* d_in, const int* in_sizes, int n_in,
                              void* d_out, int out_size) {
    const float* x  = (const float*)d_in[0];
    const float* bw = (const float*)d_in[1];
    const float* sw = (const float*)d_in[2];
    const float* ss = (const float*)d_in[3];
    float* out = (float*)d_out;

    feat_kernel<<<(B_ * CIN * HW + 255) / 256, 256>>>(x);
    fold_kernel<<<(CIN * NG * P_ * COUT + 255) / 256, 256>>>(bw, sw, ss);
    conv_kernel<<<dim3(HO, B_), 256>>>(out);
}

// round 4
// speedup vs baseline: 1.1688x; 1.1688x over previous
#include <cuda_runtime.h>
#include <cuda_bf16.h>
#include <cstdint>

// ---------------- problem constants ----------------
#define B_    16
#define CIN   32
#define COUT  64
#define HO    62
#define WO    62
#define HW    4096
#define KDIM  288          // (c,g) = 32*9
#define MTOT  65536        // b*h*w pixels
#define MPAD  65800
#define MOUT  126          // output rows per CTA
#define NCTA  521

// ---------------- device scratch ----------------
__device__ __nv_bfloat16 g_Ah[(size_t)MPAD * KDIM];
__device__ __nv_bfloat16 g_Al[(size_t)MPAD * KDIM];
__device__ __nv_bfloat16 g_Bh[9 * 64 * KDIM];       // [tap][n][k]
__device__ __nv_bfloat16 g_Bl[9 * 64 * KDIM];

// ---------------- helpers ----------------
__device__ __forceinline__ uint32_t smem_u32(const void* p) {
    uint32_t a;
    asm("{ .reg .u64 t; cvta.to.shared.u64 t, %1; cvt.u32.u64 %0, t; }" : "=r"(a) : "l"(p));
    return a;
}
__device__ __forceinline__ void cp16(uint32_t dst, const void* src) {
    asm volatile("cp.async.cg.shared.global [%0], [%1], 16;" :: "r"(dst), "l"(src));
}
#define CP_COMMIT() asm volatile("cp.async.commit_group;" ::: "memory")
#define CP_WAIT1()  asm volatile("cp.async.wait_group 1;" ::: "memory")
#define CP_WAITALL() asm volatile("cp.async.wait_all;" ::: "memory")

#define LDSM4(r, a)                                                          \
    asm volatile("ldmatrix.sync.aligned.m8n8.x4.shared.b16 {%0,%1,%2,%3}, [%4];" \
        : "=r"((r)[0]), "=r"((r)[1]), "=r"((r)[2]), "=r"((r)[3]) : "r"(a))
#define LDSM2(r, a)                                                          \
    asm volatile("ldmatrix.sync.aligned.m8n8.x2.shared.b16 {%0,%1}, [%2];"   \
        : "=r"((r)[0]), "=r"((r)[1]) : "r"(a))
#define MMA(d, a, b)                                                         \
    asm volatile("mma.sync.aligned.m16n8k16.row.col.f32.bf16.bf16.f32 "      \
        "{%0,%1,%2,%3}, {%4,%5,%6,%7}, {%8,%9}, {%0,%1,%2,%3};"              \
        : "+f"((d)[0]), "+f"((d)[1]), "+f"((d)[2]), "+f"((d)[3])             \
        : "r"((a)[0]), "r"((a)[1]), "r"((a)[2]), "r"((a)[3]),                \
          "r"((b)[0]), "r"((b)[1]))

// ---------------- kernel 1: features -> bf16 hi/lo A ----------------
__global__ void feat_kernel(const float* __restrict__ x) {
    int idx = blockIdx.x * blockDim.x + threadIdx.x;
    if (idx >= B_ * CIN * HW) return;
    float v = x[idx];
    int hw = idx & (HW - 1);
    int bc = idx >> 12;
    int c = bc & 31, b = bc >> 5;
    int m = (b << 12) | hw;

    float f[9];
    f[0] = __fdividef(v, 1.0f + __expf(-v));   // SiLU

    float t[12];
#pragma unroll
    for (int j = 0; j < 12; ++j) t[j] = (float)(j - 3) * 0.4f + (-1.0f);
    float b0[11];
#pragma unroll
    for (int i = 0; i < 11; ++i) b0[i] = (v >= t[i] && v < t[i + 1]) ? 1.0f : 0.0f;
    float b1[10];
#pragma unroll
    for (int i = 0; i < 10; ++i)
        b1[i] = __fdividef(v - t[i], t[i + 1] - t[i]) * b0[i]
              + __fdividef(t[i + 2] - v, t[i + 2] - t[i + 1]) * b0[i + 1];
    float b2[9];
#pragma unroll
    for (int i = 0; i < 9; ++i)
        b2[i] = __fdividef(v - t[i], t[i + 2] - t[i]) * b1[i]
              + __fdividef(t[i + 3] - v, t[i + 3] - t[i + 1]) * b1[i + 1];
#pragma unroll
    for (int i = 0; i < 8; ++i)
        f[i + 1] = __fdividef(v - t[i], t[i + 3] - t[i]) * b2[i]
                 + __fdividef(t[i + 4] - v, t[i + 4] - t[i + 1]) * b2[i + 1];

    size_t base = (size_t)m * KDIM + c * 9;
#pragma unroll
    for (int g = 0; g < 9; ++g) {
        float fv = f[g];
        __nv_bfloat16 hi = __float2bfloat16(fv);
        __nv_bfloat16 lo = __float2bfloat16(fv - __bfloat162float(hi));
        g_Ah[base + g] = hi;
        g_Al[base + g] = lo;
    }
}

// ---------------- kernel 2: fold + split weights ----------------
__global__ void fold_kernel(const float* __restrict__ bw,
                            const float* __restrict__ sw,
                            const float* __restrict__ ss) {
    int i = blockIdx.x * blockDim.x + threadIdx.x;    // [tap][n][k]
    if (i >= 9 * 64 * KDIM) return;
    int k = i % KDIM;
    int n = (i / KDIM) & 63;
    int p = i / (KDIM * 64);
    int c = k / 9, g = k % 9;
    int ocp = (n * CIN + c) * 9 + p;
    float val = (g == 0) ? bw[ocp] : sw[ocp * 8 + (g - 1)] * ss[ocp];
    __nv_bfloat16 hi = __float2bfloat16(val);
    g_Bh[i] = hi;
    g_Bl[i] = __float2bfloat16(val - __bfloat162float(hi));
}

// ---------------- kernel 3: mma.sync bf16 GEMM ----------------
// smem per buffer: A[2 splits][256 rows][48B pitch, 16x bf16 used] = 24576
//                  B[18 tiles][64 rows][48B pitch]                 = 55296
// double buffered: 2 * 79872 = 159744 B
#define APITCH 48
#define ASPLIT (256 * APITCH)            // 12288
#define BOFF   (2 * ASPLIT)              // 24576
#define BTILE  (64 * APITCH)             // 3072
#define BUFSZ  (BOFF + 18 * BTILE)       // 79872
#define SMEM_TOT (2 * BUFSZ)

__global__ void __launch_bounds__(256, 1) gemm_kernel(float* __restrict__ out) {
    extern __shared__ __align__(16) char smem[];
    uint32_t sb = smem_u32(smem);
    const int tid  = threadIdx.x;
    const int lane = tid & 31;
    const int wid  = tid >> 5;
    const int mw = wid & 3;              // m-warp: rows mw*32 .. +32
    const int nw = wid >> 2;             // n-warp: cols nw*32 .. +32
    const int m0 = blockIdx.x * MOUT;

    const char* Ahp = (const char*)g_Ah;
    const char* Alp = (const char*)g_Al;
    const char* Bhp = (const char*)g_Bh;
    const char* Blp = (const char*)g_Bl;

    // prefetch one k16 chunk into buffer `bb`
    auto prefetch = [&](int kc, uint32_t bb) {
#pragma unroll
        for (int i = 0; i < 13; ++i) {
            int u = tid + i * 256;                  // 13*256 == 3328 ops exactly
            const char* src;
            uint32_t dst;
            if (u < 1024) {
                int split = u >> 9, row = (u >> 1) & 255, half = u & 1;
                src = (split ? Alp : Ahp)
                    + (size_t)(m0 + row) * (KDIM * 2) + kc * 32 + half * 16;
                dst = bb + split * ASPLIT + row * APITCH + half * 16;
            } else {
                int v = u - 1024;
                int tile = v >> 7, row = (v >> 1) & 63, half = v & 1;
                int tap = tile >> 1, split = tile & 1;
                src = (split ? Blp : Bhp)
                    + (size_t)(tap * 64 + row) * (KDIM * 2) + kc * 32 + half * 16;
                dst = bb + BOFF + tile * BTILE + row * APITCH + half * 16;
            }
            cp16(dst, src);
        }
    };

    float acc[3][2][4][4];
#pragma unroll
    for (int a = 0; a < 3; ++a)
#pragma unroll
        for (int b = 0; b < 2; ++b)
#pragma unroll
            for (int c = 0; c < 4; ++c)
#pragma unroll
                for (int d = 0; d < 4; ++d) acc[a][b][c][d] = 0.0f;

    const uint32_t a_lane = (uint32_t)((lane & 15) * APITCH + (lane >> 4) * 16);
    const uint32_t b_lane = (uint32_t)((lane & 7) * APITCH + ((lane >> 3) & 1) * 16);

    prefetch(0, sb);
    CP_COMMIT();

    for (int kc = 0; kc < 18; ++kc) {
        if (kc < 17) prefetch(kc + 1, sb + ((kc + 1) & 1) * BUFSZ);
        CP_COMMIT();
        CP_WAIT1();
        __syncthreads();

        const uint32_t bb = sb + (kc & 1) * BUFSZ;
#pragma unroll
        for (int kh = 0; kh < 3; ++kh) {
            uint32_t ah[2][4], al[2][4];
#pragma unroll
            for (int t2 = 0; t2 < 2; ++t2) {
                uint32_t ra = bb + (kh * 64 + mw * 32 + t2 * 16) * APITCH + a_lane;
                LDSM4(ah[t2], ra);
                LDSM4(al[t2], ra + ASPLIT);
            }
#pragma unroll
            for (int kw = 0; kw < 3; ++kw) {
                const int tile = (kh * 3 + kw) * 2;
#pragma unroll
                for (int nf = 0; nf < 4; ++nf) {
                    uint32_t rb = bb + BOFF + tile * BTILE
                                + (nw * 32 + nf * 8) * APITCH + b_lane;
                    uint32_t bh[2], bl[2];
                    LDSM2(bh, rb);
                    LDSM2(bl, rb + BTILE);
#pragma unroll
                    for (int t2 = 0; t2 < 2; ++t2) {
                        MMA(acc[kw][t2][nf], ah[t2], bh);
                        MMA(acc[kw][t2][nf], ah[t2], bl);
                        MMA(acc[kw][t2][nf], al[t2], bh);
                    }
                }
            }
        }
        __syncthreads();
    }

    CP_WAITALL();
    __syncthreads();

    // ---- epilogue: planes D0/D1/D2 [128][65] f32, then shifted sum ----
    float* S = (float*)smem;
    const int grp = lane >> 2;
    const int cq  = (lane & 3) * 2;
#pragma unroll
    for (int kw = 0; kw < 3; ++kw) {
        float* P = S + kw * (128 * 65);
#pragma unroll
        for (int t2 = 0; t2 < 2; ++t2)
#pragma unroll
            for (int nf = 0; nf < 4; ++nf) {
                int row = mw * 32 + t2 * 16 + grp;
                int col = nw * 32 + nf * 8 + cq;
                P[row * 65 + col]           = acc[kw][t2][nf][0];
                P[row * 65 + col + 1]       = acc[kw][t2][nf][1];
                P[(row + 8) * 65 + col]     = acc[kw][t2][nf][2];
                P[(row + 8) * 65 + col + 1] = acc[kw][t2][nf][3];
            }
    }
    __syncthreads();

#pragma unroll
    for (int i = 0; i < 32; ++i) {
        int e = tid + i * 256;               // e < 8192
        int o = e >> 7, r = e & 127;
        if (r < MOUT) {
            int m = m0 + r;
            if (m < MTOT) {
                int h = (m >> 6) & 63, w = m & 63, b = m >> 12;
                if (h < HO && w < WO) {
                    float val = S[r * 65 + o]
                              + S[128 * 65 + (r + 1) * 65 + o]
                              + S[2 * 128 * 65 + (r + 2) * 65 + o];
                    out[(((size_t)(b * COUT + o)) * HO + h) * WO + w] = val;
                }
            }
        }
    }
}

// ---------------- launch ----------------
extern "C" void kernel_launch(void* const* d_in, const int* in_sizes, int n_in,
                              void* d_out, int out_size) {
    const float* x  = (const float*)d_in[0];
    const float* bw = (const float*)d_in[1];
    const float* sw = (const float*)d_in[2];
    const float* ss = (const float*)d_in[3];
    float* out = (float*)d_out;

    static int smem_set = 0;
    if (!smem_set) {
        cudaFuncSetAttribute(gemm_kernel, cudaFuncAttributeMaxDynamicSharedMemorySize, SMEM_TOT);
        smem_set = 1;
    }

    feat_kernel<<<(B_ * CIN * HW + 255) / 256, 256>>>(x);
    fold_kernel<<<(9 * 64 * KDIM + 255) / 256, 256>>>(bw, sw, ss);
    gemm_kernel<<<NCTA, 256, SMEM_TOT>>>(out);
}

// round 5
// speedup vs baseline: 2.2461x; 1.9217x over previous
#include <cuda_runtime.h>
#include <cuda_bf16.h>
#include <cstdint>

// ---------------- problem constants ----------------
#define B_    16
#define CIN   32
#define COUT  64
#define HO    62
#define WO    62
#define HW    4096
#define KDIM  288          // (c,g) = 32*9
#define MTOT  65536        // b*h*w pixels
#define MPAD  65800
#define MOUT  126          // output rows per CTA
#define NCTA  521

// ---------------- device scratch ----------------
__device__ __align__(16) __nv_bfloat16 g_Ah[(size_t)MPAD * KDIM];
__device__ __align__(16) __nv_bfloat16 g_Al[(size_t)MPAD * KDIM];
__device__ __align__(16) __nv_bfloat16 g_Bh[9 * 64 * KDIM];       // [tap][n][k]
__device__ __align__(16) __nv_bfloat16 g_Bl[9 * 64 * KDIM];

// ---------------- helpers ----------------
__device__ __forceinline__ uint32_t smem_u32(const void* p) {
    uint32_t a;
    asm("{ .reg .u64 t; cvta.to.shared.u64 t, %1; cvt.u32.u64 %0, t; }" : "=r"(a) : "l"(p));
    return a;
}
__device__ __forceinline__ void cp16(uint32_t dst, const void* src) {
    asm volatile("cp.async.cg.shared.global [%0], [%1], 16;" :: "r"(dst), "l"(src));
}
#define CP_COMMIT() asm volatile("cp.async.commit_group;" ::: "memory")
#define CP_WAIT1()  asm volatile("cp.async.wait_group 1;" ::: "memory")
#define CP_WAITALL() asm volatile("cp.async.wait_all;" ::: "memory")

#define LDSM4(r, a)                                                          \
    asm volatile("ldmatrix.sync.aligned.m8n8.x4.shared.b16 {%0,%1,%2,%3}, [%4];" \
        : "=r"((r)[0]), "=r"((r)[1]), "=r"((r)[2]), "=r"((r)[3]) : "r"(a))
#define LDSM2(r, a)                                                          \
    asm volatile("ldmatrix.sync.aligned.m8n8.x2.shared.b16 {%0,%1}, [%2];"   \
        : "=r"((r)[0]), "=r"((r)[1]) : "r"(a))
#define MMA(d, a, b)                                                         \
    asm volatile("mma.sync.aligned.m16n8k16.row.col.f32.bf16.bf16.f32 "      \
        "{%0,%1,%2,%3}, {%4,%5,%6,%7}, {%8,%9}, {%0,%1,%2,%3};"              \
        : "+f"((d)[0]), "+f"((d)[1]), "+f"((d)[2]), "+f"((d)[3])             \
        : "r"((a)[0]), "r"((a)[1]), "r"((a)[2]), "r"((a)[3]),                \
          "r"((b)[0]), "r"((b)[1]))

// ---------------- feature math (constant-reciprocal Cox-de Boor) ----------
__device__ __forceinline__ void features9(float v, float f[9]) {
    f[0] = __fdividef(v, 1.0f + __expf(-v));   // SiLU
    float t[12];
#pragma unroll
    for (int j = 0; j < 12; ++j) t[j] = (float)(j - 3) * 0.4f + (-1.0f);
    float b0[11];
#pragma unroll
    for (int i = 0; i < 11; ++i) b0[i] = (v >= t[i] && v < t[i + 1]) ? 1.0f : 0.0f;
    const float r1 = 2.5f;            // 1/0.4
    const float r2 = 1.25f;           // 1/0.8
    const float r3 = 1.0f / 1.2f;     // 1/1.2
    float b1[10];
#pragma unroll
    for (int i = 0; i < 10; ++i)
        b1[i] = (v - t[i]) * r1 * b0[i] + (t[i + 2] - v) * r1 * b0[i + 1];
    float b2[9];
#pragma unroll
    for (int i = 0; i < 9; ++i)
        b2[i] = (v - t[i]) * r2 * b1[i] + (t[i + 3] - v) * r2 * b1[i + 1];
#pragma unroll
    for (int i = 0; i < 8; ++i)
        f[i + 1] = (v - t[i]) * r3 * b2[i] + (t[i + 4] - v) * r3 * b2[i + 1];
}

// ---------------- kernel 1: features -> bf16 hi/lo A (coalesced) ----------
// block: 32 consecutive pixels x 32 channels; smem staging; uint4 writeout.
#define SROW 290   // padded row (145 words, odd -> bank-spread)
__global__ void __launch_bounds__(256) feat_kernel(const float* __restrict__ x) {
    __shared__ __nv_bfloat16 SA[32][SROW];
    __shared__ __nv_bfloat16 SL[32][SROW];
    const int m0  = blockIdx.x * 32;
    const int b   = m0 >> 12;
    const int hw0 = m0 & 4095;
    const int t   = threadIdx.x;
    const int i   = t & 31;        // pixel within block
    const int c0  = t >> 5;        // channel group

#pragma unroll
    for (int cc = 0; cc < 4; ++cc) {
        int c = c0 + cc * 8;
        float v = x[((size_t)(b * CIN + c) << 12) + hw0 + i];
        float f[9];
        features9(v, f);
#pragma unroll
        for (int g = 0; g < 9; ++g) {
            float fv = f[g];
            __nv_bfloat16 hi = __float2bfloat16(fv);
            __nv_bfloat16 lo = __float2bfloat16(fv - __bfloat162float(hi));
            SA[i][c * 9 + g] = hi;
            SL[i][c * 9 + g] = lo;
        }
    }
    __syncthreads();

    // contiguous block region: 32 rows x 288 bf16 = 1152 uint4 per array
#pragma unroll
    for (int u = t; u < 1152; u += 256) {
        int row = u / 36;
        int col = (u - row * 36) * 8;
        const uint32_t* pa = (const uint32_t*)&SA[row][col];
        uint4 va; va.x = pa[0]; va.y = pa[1]; va.z = pa[2]; va.w = pa[3];
        *(uint4*)&g_Ah[(size_t)(m0 + row) * KDIM + col] = va;
        const uint32_t* pl = (const uint32_t*)&SL[row][col];
        uint4 vl; vl.x = pl[0]; vl.y = pl[1]; vl.z = pl[2]; vl.w = pl[3];
        *(uint4*)&g_Al[(size_t)(m0 + row) * KDIM + col] = vl;
    }
}

// ---------------- kernel 2: fold + split weights ----------------
__global__ void fold_kernel(const float* __restrict__ bw,
                            const float* __restrict__ sw,
                            const float* __restrict__ ss) {
    int i = blockIdx.x * blockDim.x + threadIdx.x;    // [tap][n][k]
    if (i >= 9 * 64 * KDIM) return;
    int k = i % KDIM;
    int n = (i / KDIM) & 63;
    int p = i / (KDIM * 64);
    int c = k / 9, g = k % 9;
    int ocp = (n * CIN + c) * 9 + p;
    float val = (g == 0) ? bw[ocp] : sw[ocp * 8 + (g - 1)] * ss[ocp];
    __nv_bfloat16 hi = __float2bfloat16(val);
    g_Bh[i] = hi;
    g_Bl[i] = __float2bfloat16(val - __bfloat162float(hi));
}

// ---------------- kernel 3: mma.sync bf16 GEMM (unchanged from R4) -------
#define APITCH 48
#define ASPLIT (256 * APITCH)            // 12288
#define BOFF   (2 * ASPLIT)              // 24576
#define BTILE  (64 * APITCH)             // 3072
#define BUFSZ  (BOFF + 18 * BTILE)       // 79872
#define SMEM_TOT (2 * BUFSZ)

__global__ void __launch_bounds__(256, 1) gemm_kernel(float* __restrict__ out) {
    extern __shared__ __align__(16) char smem[];
    uint32_t sb = smem_u32(smem);
    const int tid  = threadIdx.x;
    const int lane = tid & 31;
    const int wid  = tid >> 5;
    const int mw = wid & 3;
    const int nw = wid >> 2;
    const int m0 = blockIdx.x * MOUT;

    const char* Ahp = (const char*)g_Ah;
    const char* Alp = (const char*)g_Al;
    const char* Bhp = (const char*)g_Bh;
    const char* Blp = (const char*)g_Bl;

    auto prefetch = [&](int kc, uint32_t bb) {
#pragma unroll
        for (int i = 0; i < 13; ++i) {
            int u = tid + i * 256;
            const char* src;
            uint32_t dst;
            if (u < 1024) {
                int split = u >> 9, row = (u >> 1) & 255, half = u & 1;
                src = (split ? Alp : Ahp)
                    + (size_t)(m0 + row) * (KDIM * 2) + kc * 32 + half * 16;
                dst = bb + split * ASPLIT + row * APITCH + half * 16;
            } else {
                int v = u - 1024;
                int tile = v >> 7, row = (v >> 1) & 63, half = v & 1;
                int tap = tile >> 1, split = tile & 1;
                src = (split ? Blp : Bhp)
                    + (size_t)(tap * 64 + row) * (KDIM * 2) + kc * 32 + half * 16;
                dst = bb + BOFF + tile * BTILE + row * APITCH + half * 16;
            }
            cp16(dst, src);
        }
    };

    float acc[3][2][4][4];
#pragma unroll
    for (int a = 0; a < 3; ++a)
#pragma unroll
        for (int b = 0; b < 2; ++b)
#pragma unroll
            for (int c = 0; c < 4; ++c)
#pragma unroll
                for (int d = 0; d < 4; ++d) acc[a][b][c][d] = 0.0f;

    const uint32_t a_lane = (uint32_t)((lane & 15) * APITCH + (lane >> 4) * 16);
    const uint32_t b_lane = (uint32_t)((lane & 7) * APITCH + ((lane >> 3) & 1) * 16);

    prefetch(0, sb);
    CP_COMMIT();

    for (int kc = 0; kc < 18; ++kc) {
        if (kc < 17) prefetch(kc + 1, sb + ((kc + 1) & 1) * BUFSZ);
        CP_COMMIT();
        CP_WAIT1();
        __syncthreads();

        const uint32_t bb = sb + (kc & 1) * BUFSZ;
#pragma unroll
        for (int kh = 0; kh < 3; ++kh) {
            uint32_t ah[2][4], al[2][4];
#pragma unroll
            for (int t2 = 0; t2 < 2; ++t2) {
                uint32_t ra = bb + (kh * 64 + mw * 32 + t2 * 16) * APITCH + a_lane;
                LDSM4(ah[t2], ra);
                LDSM4(al[t2], ra + ASPLIT);
            }
#pragma unroll
            for (int kw = 0; kw < 3; ++kw) {
                const int tile = (kh * 3 + kw) * 2;
#pragma unroll
                for (int nf = 0; nf < 4; ++nf) {
                    uint32_t rb = bb + BOFF + tile * BTILE
                                + (nw * 32 + nf * 8) * APITCH + b_lane;
                    uint32_t bh[2], bl[2];
                    LDSM2(bh, rb);
                    LDSM2(bl, rb + BTILE);
#pragma unroll
                    for (int t2 = 0; t2 < 2; ++t2) {
                        MMA(acc[kw][t2][nf], ah[t2], bh);
                        MMA(acc[kw][t2][nf], ah[t2], bl);
                        MMA(acc[kw][t2][nf], al[t2], bh);
                    }
                }
            }
        }
        __syncthreads();
    }

    CP_WAITALL();
    __syncthreads();

    // ---- epilogue ----
    float* S = (float*)smem;
    const int grp = lane >> 2;
    const int cq  = (lane & 3) * 2;
#pragma unroll
    for (int kw = 0; kw < 3; ++kw) {
        float* P = S + kw * (128 * 65);
#pragma unroll
        for (int t2 = 0; t2 < 2; ++t2)
#pragma unroll
            for (int nf = 0; nf < 4; ++nf) {
                int row = mw * 32 + t2 * 16 + grp;
                int col = nw * 32 + nf * 8 + cq;
                P[row * 65 + col]           = acc[kw][t2][nf][0];
                P[row * 65 + col + 1]       = acc[kw][t2][nf][1];
                P[(row + 8) * 65 + col]     = acc[kw][t2][nf][2];
                P[(row + 8) * 65 + col + 1] = acc[kw][t2][nf][3];
            }
    }
    __syncthreads();

#pragma unroll
    for (int i = 0; i < 32; ++i) {
        int e = tid + i * 256;
        int o = e >> 7, r = e & 127;
        if (r < MOUT) {
            int m = m0 + r;
            if (m < MTOT) {
                int h = (m >> 6) & 63, w = m & 63, b = m >> 12;
                if (h < HO && w < WO) {
                    float val = S[r * 65 + o]
                              + S[128 * 65 + (r + 1) * 65 + o]
                              + S[2 * 128 * 65 + (r + 2) * 65 + o];
                    out[(((size_t)(b * COUT + o)) * HO + h) * WO + w] = val;
                }
            }
        }
    }
}

// ---------------- launch ----------------
extern "C" void kernel_launch(void* const* d_in, const int* in_sizes, int n_in,
                              void* d_out, int out_size) {
    const float* x  = (const float*)d_in[0];
    const float* bw = (const float*)d_in[1];
    const float* sw = (const float*)d_in[2];
    const float* ss = (const float*)d_in[3];
    float* out = (float*)d_out;

    static int smem_set = 0;
    if (!smem_set) {
        cudaFuncSetAttribute(gemm_kernel, cudaFuncAttributeMaxDynamicSharedMemorySize, SMEM_TOT);
        smem_set = 1;
    }

    feat_kernel<<<MTOT / 32, 256>>>(x);
    fold_kernel<<<(9 * 64 * KDIM + 255) / 256, 256>>>(bw, sw, ss);
    gemm_kernel<<<NCTA, 256, SMEM_TOT>>>(out);
}

// round 6
// speedup vs baseline: 2.9472x; 1.3121x over previous
#include <cuda_runtime.h>
#include <cuda_fp16.h>
#include <cstdint>

// ---------------- problem constants ----------------
#define B_    16
#define CIN   32
#define COUT  64
#define HO    62
#define WO    62
#define HW    4096
#define KDIM  288          // (c,g) = 32*9
#define MTOT  65536        // b*h*w pixels
#define MPAD  65800
#define MOUT  126          // output rows per CTA
#define NCTA  521

// ---------------- device scratch ----------------
__device__ __align__(16) __half g_A [(size_t)MPAD * KDIM];   // fp16 features
__device__ __align__(16) __half g_Bh[9 * 64 * KDIM];         // [tap][n][k] hi
__device__ __align__(16) __half g_Bl[9 * 64 * KDIM];         // [tap][n][k] lo

// ---------------- helpers ----------------
__device__ __forceinline__ uint32_t smem_u32(const void* p) {
    uint32_t a;
    asm("{ .reg .u64 t; cvta.to.shared.u64 t, %1; cvt.u32.u64 %0, t; }" : "=r"(a) : "l"(p));
    return a;
}
__device__ __forceinline__ void cp16(uint32_t dst, const void* src) {
    asm volatile("cp.async.cg.shared.global [%0], [%1], 16;" :: "r"(dst), "l"(src));
}
#define CP_COMMIT() asm volatile("cp.async.commit_group;" ::: "memory")
#define CP_WAIT1()  asm volatile("cp.async.wait_group 1;" ::: "memory")
#define CP_WAITALL() asm volatile("cp.async.wait_all;" ::: "memory")

#define LDSM4(r, a)                                                          \
    asm volatile("ldmatrix.sync.aligned.m8n8.x4.shared.b16 {%0,%1,%2,%3}, [%4];" \
        : "=r"((r)[0]), "=r"((r)[1]), "=r"((r)[2]), "=r"((r)[3]) : "r"(a))
#define LDSM2(r, a)                                                          \
    asm volatile("ldmatrix.sync.aligned.m8n8.x2.shared.b16 {%0,%1}, [%2];"   \
        : "=r"((r)[0]), "=r"((r)[1]) : "r"(a))
#define MMA(d, a, b)                                                         \
    asm volatile("mma.sync.aligned.m16n8k16.row.col.f32.f16.f16.f32 "        \
        "{%0,%1,%2,%3}, {%4,%5,%6,%7}, {%8,%9}, {%0,%1,%2,%3};"              \
        : "+f"((d)[0]), "+f"((d)[1]), "+f"((d)[2]), "+f"((d)[3])             \
        : "r"((a)[0]), "r"((a)[1]), "r"((a)[2]), "r"((a)[3]),                \
          "r"((b)[0]), "r"((b)[1]))

// ---------------- feature math (constant-reciprocal Cox-de Boor) ----------
__device__ __forceinline__ void features9(float v, float f[9]) {
    f[0] = __fdividef(v, 1.0f + __expf(-v));   // SiLU
    float t[12];
#pragma unroll
    for (int j = 0; j < 12; ++j) t[j] = (float)(j - 3) * 0.4f + (-1.0f);
    float b0[11];
#pragma unroll
    for (int i = 0; i < 11; ++i) b0[i] = (v >= t[i] && v < t[i + 1]) ? 1.0f : 0.0f;
    const float r1 = 2.5f;
    const float r2 = 1.25f;
    const float r3 = 1.0f / 1.2f;
    float b1[10];
#pragma unroll
    for (int i = 0; i < 10; ++i)
        b1[i] = (v - t[i]) * r1 * b0[i] + (t[i + 2] - v) * r1 * b0[i + 1];
    float b2[9];
#pragma unroll
    for (int i = 0; i < 9; ++i)
        b2[i] = (v - t[i]) * r2 * b1[i] + (t[i + 3] - v) * r2 * b1[i + 1];
#pragma unroll
    for (int i = 0; i < 8; ++i)
        f[i + 1] = (v - t[i]) * r3 * b2[i] + (t[i + 4] - v) * r3 * b2[i + 1];
}

// ---------------- kernel 1: features -> fp16 A (coalesced) ----------------
#define SROW 290
__global__ void __launch_bounds__(256) feat_kernel(const float* __restrict__ x) {
    __shared__ __half SA[32][SROW];
    const int m0  = blockIdx.x * 32;
    const int b   = m0 >> 12;
    const int hw0 = m0 & 4095;
    const int t   = threadIdx.x;
    const int i   = t & 31;
    const int c0  = t >> 5;

#pragma unroll
    for (int cc = 0; cc < 4; ++cc) {
        int c = c0 + cc * 8;
        float v = x[((size_t)(b * CIN + c) << 12) + hw0 + i];
        float f[9];
        features9(v, f);
#pragma unroll
        for (int g = 0; g < 9; ++g) SA[i][c * 9 + g] = __float2half(f[g]);
    }
    __syncthreads();

#pragma unroll
    for (int u = t; u < 1152; u += 256) {
        int row = u / 36;
        int col = (u - row * 36) * 8;
        const uint32_t* pa = (const uint32_t*)&SA[row][col];
        uint4 va; va.x = pa[0]; va.y = pa[1]; va.z = pa[2]; va.w = pa[3];
        *(uint4*)&g_A[(size_t)(m0 + row) * KDIM + col] = va;
    }
}

// ---------------- kernel 2: fold + fp16 hi/lo split weights ---------------
__global__ void fold_kernel(const float* __restrict__ bw,
                            const float* __restrict__ sw,
                            const float* __restrict__ ss) {
    int i = blockIdx.x * blockDim.x + threadIdx.x;    // [tap][n][k]
    if (i >= 9 * 64 * KDIM) return;
    int k = i % KDIM;
    int n = (i / KDIM) & 63;
    int p = i / (KDIM * 64);
    int c = k / 9, g = k % 9;
    int ocp = (n * CIN + c) * 9 + p;
    float val = (g == 0) ? bw[ocp] : sw[ocp * 8 + (g - 1)] * ss[ocp];
    __half hi = __float2half(val);
    g_Bh[i] = hi;
    g_Bl[i] = __float2half(val - __half2float(hi));
}

// ---------------- kernel 3: mma.sync fp16 GEMM (2-term) --------------------
// smem per buffer: A[256 rows][48B pitch]   = 12288
//                  B[18 tiles][64 rows][48] = 55296
// double buffered: 2 * 67584 = 135168 B
#define APITCH 48
#define BOFF   (256 * APITCH)            // 12288
#define BTILE  (64 * APITCH)             // 3072
#define BUFSZ  (BOFF + 18 * BTILE)       // 67584
#define SMEM_TOT (2 * BUFSZ)

__global__ void __launch_bounds__(256, 1) gemm_kernel(float* __restrict__ out) {
    extern __shared__ __align__(16) char smem[];
    uint32_t sb = smem_u32(smem);
    const int tid  = threadIdx.x;
    const int lane = tid & 31;
    const int wid  = tid >> 5;
    const int mw = wid & 3;
    const int nw = wid >> 2;
    const int m0 = blockIdx.x * MOUT;

    const char* Ap  = (const char*)g_A;
    const char* Bhp = (const char*)g_Bh;
    const char* Blp = (const char*)g_Bl;

    auto prefetch = [&](int kc, uint32_t bb) {
#pragma unroll
        for (int i = 0; i < 11; ++i) {
            int u = tid + i * 256;                   // 11*256 == 2816 exactly
            const char* src;
            uint32_t dst;
            if (u < 512) {
                int row = u >> 1, half = u & 1;
                src = Ap + (size_t)(m0 + row) * (KDIM * 2) + kc * 32 + half * 16;
                dst = bb + row * APITCH + half * 16;
            } else {
                int v = u - 512;
                int tile = v >> 7, row = (v >> 1) & 63, half = v & 1;
                int tap = tile >> 1, split = tile & 1;
                src = (split ? Blp : Bhp)
                    + (size_t)(tap * 64 + row) * (KDIM * 2) + kc * 32 + half * 16;
                dst = bb + BOFF + tile * BTILE + row * APITCH + half * 16;
            }
            cp16(dst, src);
        }
    };

    float acc[3][2][4][4];
#pragma unroll
    for (int a = 0; a < 3; ++a)
#pragma unroll
        for (int b = 0; b < 2; ++b)
#pragma unroll
            for (int c = 0; c < 4; ++c)
#pragma unroll
                for (int d = 0; d < 4; ++d) acc[a][b][c][d] = 0.0f;

    const uint32_t a_lane = (uint32_t)((lane & 15) * APITCH + (lane >> 4) * 16);
    const uint32_t b_lane = (uint32_t)((lane & 7) * APITCH + ((lane >> 3) & 1) * 16);

    prefetch(0, sb);
    CP_COMMIT();

    for (int kc = 0; kc < 18; ++kc) {
        if (kc < 17) prefetch(kc + 1, sb + ((kc + 1) & 1) * BUFSZ);
        CP_COMMIT();
        CP_WAIT1();
        __syncthreads();

        const uint32_t bb = sb + (kc & 1) * BUFSZ;
#pragma unroll
        for (int kh = 0; kh < 3; ++kh) {
            uint32_t ah[2][4];
#pragma unroll
            for (int t2 = 0; t2 < 2; ++t2) {
                uint32_t ra = bb + (kh * 64 + mw * 32 + t2 * 16) * APITCH + a_lane;
                LDSM4(ah[t2], ra);
            }
#pragma unroll
            for (int kw = 0; kw < 3; ++kw) {
                const int tile = (kh * 3 + kw) * 2;
#pragma unroll
                for (int nf = 0; nf < 4; ++nf) {
                    uint32_t rb = bb + BOFF + tile * BTILE
                                + (nw * 32 + nf * 8) * APITCH + b_lane;
                    uint32_t bh[2], bl[2];
                    LDSM2(bh, rb);
                    LDSM2(bl, rb + BTILE);
#pragma unroll
                    for (int t2 = 0; t2 < 2; ++t2) {
                        MMA(acc[kw][t2][nf], ah[t2], bh);
                        MMA(acc[kw][t2][nf], ah[t2], bl);
                    }
                }
            }
        }
        __syncthreads();
    }

    CP_WAITALL();
    __syncthreads();

    // ---- epilogue: planes D0/D1/D2 [128][65] f32, then shifted sum ----
    float* S = (float*)smem;
    const int grp = lane >> 2;
    const int cq  = (lane & 3) * 2;
#pragma unroll
    for (int kw = 0; kw < 3; ++kw) {
        float* P = S + kw * (128 * 65);
#pragma unroll
        for (int t2 = 0; t2 < 2; ++t2)
#pragma unroll
            for (int nf = 0; nf < 4; ++nf) {
                int row = mw * 32 + t2 * 16 + grp;
                int col = nw * 32 + nf * 8 + cq;
                P[row * 65 + col]           = acc[kw][t2][nf][0];
                P[row * 65 + col + 1]       = acc[kw][t2][nf][1];
                P[(row + 8) * 65 + col]     = acc[kw][t2][nf][2];
                P[(row + 8) * 65 + col + 1] = acc[kw][t2][nf][3];
            }
    }
    __syncthreads();

#pragma unroll
    for (int i = 0; i < 32; ++i) {
        int e = tid + i * 256;
        int o = e >> 7, r = e & 127;
        if (r < MOUT) {
            int m = m0 + r;
            if (m < MTOT) {
                int h = (m >> 6) & 63, w = m & 63, b = m >> 12;
                if (h < HO && w < WO) {
                    float val = S[r * 65 + o]
                              + S[128 * 65 + (r + 1) * 65 + o]
                              + S[2 * 128 * 65 + (r + 2) * 65 + o];
                    out[(((size_t)(b * COUT + o)) * HO + h) * WO + w] = val;
                }
            }
        }
    }
}

// ---------------- launch ----------------
extern "C" void kernel_launch(void* const* d_in, const int* in_sizes, int n_in,
                              void* d_out, int out_size) {
    const float* x  = (const float*)d_in[0];
    const float* bw = (const float*)d_in[1];
    const float* sw = (const float*)d_in[2];
    const float* ss = (const float*)d_in[3];
    float* out = (float*)d_out;

    static int smem_set = 0;
    if (!smem_set) {
        cudaFuncSetAttribute(gemm_kernel, cudaFuncAttributeMaxDynamicSharedMemorySize, SMEM_TOT);
        smem_set = 1;
    }

    feat_kernel<<<MTOT / 32, 256>>>(x);
    fold_kernel<<<(9 * 64 * KDIM + 255) / 256, 256>>>(bw, sw, ss);
    gemm_kernel<<<NCTA, 256, SMEM_TOT>>>(out);
}

// round 7
// speedup vs baseline: 4.5139x; 1.5316x over previous
#include <cuda_runtime.h>
#include <cuda_fp16.h>
#include <cstdint>

// ---------------- problem constants ----------------
#define B_    16
#define CIN   32
#define COUT  64
#define HO    62
#define WO    62
#define HW    4096
#define KDIM  288          // (c,g) = 32*9
#define MTOT  65536        // b*h*w pixels
#define MPAD  65800
#define MOUT  126          // output rows per CTA
#define NCTA  521

// ---------------- device scratch ----------------
__device__ __align__(16) __half g_A[(size_t)MPAD * KDIM];   // fp16 features
__device__ __align__(16) __half g_B[9 * 64 * KDIM];         // [tap][n][k] fp16

// ---------------- helpers ----------------
__device__ __forceinline__ uint32_t smem_u32(const void* p) {
    uint32_t a;
    asm("{ .reg .u64 t; cvta.to.shared.u64 t, %1; cvt.u32.u64 %0, t; }" : "=r"(a) : "l"(p));
    return a;
}
__device__ __forceinline__ void cp16(uint32_t dst, const void* src) {
    asm volatile("cp.async.cg.shared.global [%0], [%1], 16;" :: "r"(dst), "l"(src));
}
#define CP_COMMIT() asm volatile("cp.async.commit_group;" ::: "memory")
#define CP_WAIT1()  asm volatile("cp.async.wait_group 1;" ::: "memory")
#define CP_WAITALL() asm volatile("cp.async.wait_all;" ::: "memory")

#define LDSM4(r, a)                                                          \
    asm volatile("ldmatrix.sync.aligned.m8n8.x4.shared.b16 {%0,%1,%2,%3}, [%4];" \
        : "=r"((r)[0]), "=r"((r)[1]), "=r"((r)[2]), "=r"((r)[3]) : "r"(a))
#define LDSM2(r, a)                                                          \
    asm volatile("ldmatrix.sync.aligned.m8n8.x2.shared.b16 {%0,%1}, [%2];"   \
        : "=r"((r)[0]), "=r"((r)[1]) : "r"(a))
#define MMA(d, a, b)                                                         \
    asm volatile("mma.sync.aligned.m16n8k16.row.col.f32.f16.f16.f32 "        \
        "{%0,%1,%2,%3}, {%4,%5,%6,%7}, {%8,%9}, {%0,%1,%2,%3};"              \
        : "+f"((d)[0]), "+f"((d)[1]), "+f"((d)[2]), "+f"((d)[3])             \
        : "r"((a)[0]), "r"((a)[1]), "r"((a)[2]), "r"((a)[3]),                \
          "r"((b)[0]), "r"((b)[1]))

// ---------------- feature math (constant-reciprocal Cox-de Boor) ----------
__device__ __forceinline__ void features9(float v, float f[9]) {
    f[0] = __fdividef(v, 1.0f + __expf(-v));   // SiLU
    float t[12];
#pragma unroll
    for (int j = 0; j < 12; ++j) t[j] = (float)(j - 3) * 0.4f + (-1.0f);
    float b0[11];
#pragma unroll
    for (int i = 0; i < 11; ++i) b0[i] = (v >= t[i] && v < t[i + 1]) ? 1.0f : 0.0f;
    const float r1 = 2.5f;
    const float r2 = 1.25f;
    const float r3 = 1.0f / 1.2f;
    float b1[10];
#pragma unroll
    for (int i = 0; i < 10; ++i)
        b1[i] = (v - t[i]) * r1 * b0[i] + (t[i + 2] - v) * r1 * b0[i + 1];
    float b2[9];
#pragma unroll
    for (int i = 0; i < 9; ++i)
        b2[i] = (v - t[i]) * r2 * b1[i] + (t[i + 3] - v) * r2 * b1[i + 1];
#pragma unroll
    for (int i = 0; i < 8; ++i)
        f[i + 1] = (v - t[i]) * r3 * b2[i] + (t[i + 4] - v) * r3 * b2[i + 1];
}

// ---------------- kernel 1: features -> fp16 A (coalesced) ----------------
#define SROW 290
__global__ void __launch_bounds__(256) feat_kernel(const float* __restrict__ x) {
    __shared__ __half SA[32][SROW];
    const int m0  = blockIdx.x * 32;
    const int b   = m0 >> 12;
    const int hw0 = m0 & 4095;
    const int t   = threadIdx.x;
    const int i   = t & 31;
    const int c0  = t >> 5;

#pragma unroll
    for (int cc = 0; cc < 4; ++cc) {
        int c = c0 + cc * 8;
        float v = x[((size_t)(b * CIN + c) << 12) + hw0 + i];
        float f[9];
        features9(v, f);
#pragma unroll
        for (int g = 0; g < 9; ++g) SA[i][c * 9 + g] = __float2half(f[g]);
    }
    __syncthreads();

#pragma unroll
    for (int u = t; u < 1152; u += 256) {
        int row = u / 36;
        int col = (u - row * 36) * 8;
        const uint32_t* pa = (const uint32_t*)&SA[row][col];
        uint4 va; va.x = pa[0]; va.y = pa[1]; va.z = pa[2]; va.w = pa[3];
        *(uint4*)&g_A[(size_t)(m0 + row) * KDIM + col] = va;
    }
}

// ---------------- kernel 2: fold weights -> fp16 ----------------
__global__ void fold_kernel(const float* __restrict__ bw,
                            const float* __restrict__ sw,
                            const float* __restrict__ ss) {
    int i = blockIdx.x * blockDim.x + threadIdx.x;    // [tap][n][k]
    if (i >= 9 * 64 * KDIM) return;
    int k = i % KDIM;
    int n = (i / KDIM) & 63;
    int p = i / (KDIM * 64);
    int c = k / 9, g = k % 9;
    int ocp = (n * CIN + c) * 9 + p;
    float val = (g == 0) ? bw[ocp] : sw[ocp * 8 + (g - 1)] * ss[ocp];
    g_B[i] = __float2half(val);
}

// ---------------- kernel 3: mma.sync fp16 GEMM (single-term) ---------------
// smem per buffer: A[256 rows][48B pitch]  = 12288
//                  B[9 tiles][64 rows][48] = 27648
// double buffered: 2 * 39936 = 79872; epilogue needs 99840 -> SMEM_TOT 99840
#define APITCH 48
#define BOFF   (256 * APITCH)            // 12288
#define BTILE  (64 * APITCH)             // 3072
#define BUFSZ  (BOFF + 9 * BTILE)        // 39936
#define SMEM_TOT (3 * 128 * 65 * 4)      // 99840

__global__ void __launch_bounds__(256, 1) gemm_kernel(float* __restrict__ out) {
    extern __shared__ __align__(16) char smem[];
    uint32_t sb = smem_u32(smem);
    const int tid  = threadIdx.x;
    const int lane = tid & 31;
    const int wid  = tid >> 5;
    const int mw = wid & 3;
    const int nw = wid >> 2;
    const int m0 = blockIdx.x * MOUT;

    const char* Ap = (const char*)g_A;
    const char* Bp = (const char*)g_B;

    auto prefetch = [&](int kc, uint32_t bb) {
#pragma unroll
        for (int i = 0; i < 7; ++i) {
            int u = tid + i * 256;                   // need 1664 total
            if (u >= 1664) break;
            const char* src;
            uint32_t dst;
            if (u < 512) {
                int row = u >> 1, half = u & 1;
                src = Ap + (size_t)(m0 + row) * (KDIM * 2) + kc * 32 + half * 16;
                dst = bb + row * APITCH + half * 16;
            } else {
                int v = u - 512;
                int tile = v >> 7, row = (v >> 1) & 63, half = v & 1;
                src = Bp + (size_t)(tile * 64 + row) * (KDIM * 2) + kc * 32 + half * 16;
                dst = bb + BOFF + tile * BTILE + row * APITCH + half * 16;
            }
            cp16(dst, src);
        }
    };

    float acc[3][2][4][4];
#pragma unroll
    for (int a = 0; a < 3; ++a)
#pragma unroll
        for (int b = 0; b < 2; ++b)
#pragma unroll
            for (int c = 0; c < 4; ++c)
#pragma unroll
                for (int d = 0; d < 4; ++d) acc[a][b][c][d] = 0.0f;

    const uint32_t a_lane = (uint32_t)((lane & 15) * APITCH + (lane >> 4) * 16);
    const uint32_t b_lane = (uint32_t)((lane & 7) * APITCH + ((lane >> 3) & 1) * 16);

    prefetch(0, sb);
    CP_COMMIT();

    for (int kc = 0; kc < 18; ++kc) {
        if (kc < 17) prefetch(kc + 1, sb + ((kc + 1) & 1) * BUFSZ);
        CP_COMMIT();
        CP_WAIT1();
        __syncthreads();

        const uint32_t bb = sb + (kc & 1) * BUFSZ;
#pragma unroll
        for (int kh = 0; kh < 3; ++kh) {
            uint32_t ah[2][4];
#pragma unroll
            for (int t2 = 0; t2 < 2; ++t2) {
                uint32_t ra = bb + (kh * 64 + mw * 32 + t2 * 16) * APITCH + a_lane;
                LDSM4(ah[t2], ra);
            }
#pragma unroll
            for (int kw = 0; kw < 3; ++kw) {
                const int tile = kh * 3 + kw;
#pragma unroll
                for (int nf = 0; nf < 4; ++nf) {
                    uint32_t rb = bb + BOFF + tile * BTILE
                                + (nw * 32 + nf * 8) * APITCH + b_lane;
                    uint32_t bfr[2];
                    LDSM2(bfr, rb);
#pragma unroll
                    for (int t2 = 0; t2 < 2; ++t2)
                        MMA(acc[kw][t2][nf], ah[t2], bfr);
                }
            }
        }
        __syncthreads();
    }

    CP_WAITALL();
    __syncthreads();

    // ---- epilogue: planes D0/D1/D2 [128][65] f32, then shifted sum ----
    float* S = (float*)smem;
    const int grp = lane >> 2;
    const int cq  = (lane & 3) * 2;
#pragma unroll
    for (int kw = 0; kw < 3; ++kw) {
        float* P = S + kw * (128 * 65);
#pragma unroll
        for (int t2 = 0; t2 < 2; ++t2)
#pragma unroll
            for (int nf = 0; nf < 4; ++nf) {
                int row = mw * 32 + t2 * 16 + grp;
                int col = nw * 32 + nf * 8 + cq;
                P[row * 65 + col]           = acc[kw][t2][nf][0];
                P[row * 65 + col + 1]       = acc[kw][t2][nf][1];
                P[(row + 8) * 65 + col]     = acc[kw][t2][nf][2];
                P[(row + 8) * 65 + col + 1] = acc[kw][t2][nf][3];
            }
    }
    __syncthreads();

#pragma unroll
    for (int i = 0; i < 32; ++i) {
        int e = tid + i * 256;
        int o = e >> 7, r = e & 127;
        if (r < MOUT) {
            int m = m0 + r;
            if (m < MTOT) {
                int h = (m >> 6) & 63, w = m & 63, b = m >> 12;
                if (h < HO && w < WO) {
                    float val = S[r * 65 + o]
                              + S[128 * 65 + (r + 1) * 65 + o]
                              + S[2 * 128 * 65 + (r + 2) * 65 + o];
                    out[(((size_t)(b * COUT + o)) * HO + h) * WO + w] = val;
                }
            }
        }
    }
}

// ---------------- launch ----------------
extern "C" void kernel_launch(void* const* d_in, const int* in_sizes, int n_in,
                              void* d_out, int out_size) {
    const float* x  = (const float*)d_in[0];
    const float* bw = (const float*)d_in[1];
    const float* sw = (const float*)d_in[2];
    const float* ss = (const float*)d_in[3];
    float* out = (float*)d_out;

    static int smem_set = 0;
    if (!smem_set) {
        cudaFuncSetAttribute(gemm_kernel, cudaFuncAttributeMaxDynamicSharedMemorySize, SMEM_TOT);
        smem_set = 1;
    }

    feat_kernel<<<MTOT / 32, 256>>>(x);
    fold_kernel<<<(9 * 64 * KDIM + 255) / 256, 256>>>(bw, sw, ss);
    gemm_kernel<<<NCTA, 256, SMEM_TOT>>>(out);
}